// round 1
// baseline (speedup 1.0000x reference)
#include <cuda_runtime.h>
#include <math.h>

// Problem constants
#define B   256
#define T1  127          // T-1 timesteps
#define D   512
#define H   512
#define G   2048         // 4*H gates
#define NL  3
#define OUT_ENC ((size_t)B * T1 * D)   // offset of input_encoded in d_out

// Persistent-kernel config
#define GRID 128
#define NT   256

// ---------------------------------------------------------------------------
// Scratch (device globals: allocation-free rule)
// ---------------------------------------------------------------------------
__device__ float g_pre0[(size_t)T1 * B * G];   // precomputed x@W_ih0^T + biases, [t][b][j]
__device__ float g_h[NL][B * H];
__device__ float g_c[NL][B * H];
__device__ float g_gates[NL][B * G];
__device__ unsigned g_bar_count;
__device__ unsigned g_gen;

// ---------------------------------------------------------------------------
// Software grid barrier (all GRID blocks guaranteed co-resident: GRID<=148,
// 1 small CTA per SM)
// ---------------------------------------------------------------------------
__device__ __forceinline__ void grid_barrier() {
    __syncthreads();
    if (threadIdx.x == 0) {
        __threadfence();
        unsigned gen = *(volatile unsigned*)&g_gen;
        unsigned arrived = atomicAdd(&g_bar_count, 1u);
        if (arrived == GRID - 1) {
            g_bar_count = 0;
            __threadfence();
            *(volatile unsigned*)&g_gen = gen + 1;
        } else {
            while (*(volatile unsigned*)&g_gen == gen) {}
        }
        __threadfence();
    }
    __syncthreads();
}

// ---------------------------------------------------------------------------
// 64x64 output tile GEMM: acc[4][4] += A[row0:row0+64, 0:512] * W[col0:col0+64, 0:512]^T
// A row-major with stride lda, W row-major with stride ldw (weights are [2048,512]).
// 256 threads, 4x4 microtile each. K fixed at 512.
// ---------------------------------------------------------------------------
__device__ __forceinline__ void mm_tile(const float* __restrict__ A, int lda,
                                        const float* __restrict__ W, int ldw,
                                        int row0, int col0,
                                        float acc[4][4], float* sA, float* sB) {
    const int t  = threadIdx.x;
    const int lm = t >> 2;           // 0..63 (row within tile for loading)
    const int lk = (t & 3) << 2;     // 0,4,8,12 (k offset within 16-chunk)
    const int tx = t & 15;           // n position
    const int ty = t >> 4;           // m position
    const float* Arow = A + (size_t)(row0 + lm) * lda + lk;
    const float* Wrow = W + (size_t)(col0 + lm) * ldw + lk;

    for (int kc = 0; kc < 512; kc += 16) {
        float4 a = *(const float4*)(Arow + kc);
        float4 b = *(const float4*)(Wrow + kc);
        __syncthreads();
        sA[(lk + 0) * 64 + lm] = a.x;
        sA[(lk + 1) * 64 + lm] = a.y;
        sA[(lk + 2) * 64 + lm] = a.z;
        sA[(lk + 3) * 64 + lm] = a.w;
        sB[(lk + 0) * 64 + lm] = b.x;
        sB[(lk + 1) * 64 + lm] = b.y;
        sB[(lk + 2) * 64 + lm] = b.z;
        sB[(lk + 3) * 64 + lm] = b.w;
        __syncthreads();
#pragma unroll
        for (int kk = 0; kk < 16; kk++) {
            float4 av = *(const float4*)(sA + kk * 64 + ty * 4);
            float4 bv = *(const float4*)(sB + kk * 64 + tx * 4);
            float ar[4] = {av.x, av.y, av.z, av.w};
            float br[4] = {bv.x, bv.y, bv.z, bv.w};
#pragma unroll
            for (int i = 0; i < 4; i++)
#pragma unroll
                for (int j = 0; j < 4; j++)
                    acc[i][j] += ar[i] * br[j];
        }
    }
}

__device__ __forceinline__ float sigm(float x) { return 1.f / (1.f + expf(-x)); }

// Elementwise LSTM cell update for layer l at step t (grid-strided)
__device__ __forceinline__ void lstm_ew(int l, int t, float* __restrict__ out) {
    for (int idx = blockIdx.x * NT + threadIdx.x; idx < B * H; idx += GRID * NT) {
        int b = idx >> 9;
        int k = idx & 511;
        const float* gb = &g_gates[l][(size_t)b * G];
        float ig = sigm(gb[k]);
        float fg = sigm(gb[H + k]);
        float gg = tanhf(gb[2 * H + k]);
        float og = sigm(gb[3 * H + k]);
        float c  = fg * g_c[l][idx] + ig * gg;
        float h  = og * tanhf(c);
        g_c[l][idx] = c;
        g_h[l][idx] = h;
        if (l == NL - 1)
            out[OUT_ENC + (size_t)b * T1 * H + (size_t)t * H + k] = h;
    }
}

// ---------------------------------------------------------------------------
// Kernel 1: attention weights + input_weighted output.
// Key identity: the h0/c0 attention terms are constant across d, and softmax is
// shift-invariant => attn[b,d] = softmax_d( sum_t x[b,t,d]*attn_w[2H+t] ),
// identical for every timestep. input_weighted[b,t,d] = attn[b,d]*x[b,t,d].
// ---------------------------------------------------------------------------
__global__ void attn_kernel(const float* __restrict__ x, const float* __restrict__ aw,
                            float* __restrict__ out) {
    __shared__ float saw[T1];
    __shared__ float red[512];
    int b = blockIdx.x, d = threadIdx.x;
    if (d < T1) saw[d] = aw[2 * H + d];
    __syncthreads();
    const float* xb = x + (size_t)b * T1 * D;
    float acc = 0.f;
    for (int t = 0; t < T1; t++) acc += xb[(size_t)t * D + d] * saw[t];
    red[d] = acc;
    __syncthreads();
    for (int s = 256; s > 0; s >>= 1) {
        if (d < s) red[d] = fmaxf(red[d], red[d + s]);
        __syncthreads();
    }
    float mx = red[0];
    __syncthreads();
    float e = expf(acc - mx);
    red[d] = e;
    __syncthreads();
    for (int s = 256; s > 0; s >>= 1) {
        if (d < s) red[d] += red[d + s];
        __syncthreads();
    }
    float a = e / red[0];
    float* ob = out + (size_t)b * T1 * D;
    for (int t = 0; t < T1; t++) ob[(size_t)t * D + d] = a * xb[(size_t)t * D + d];
}

// ---------------------------------------------------------------------------
// Kernel 2: precompute pre0[t][b][:] = weighted[b,t,:] @ W_ih[0]^T + b_ih0 + b_hh0
// One big [32512 x 512] x [512 x 2048] GEMM, time-parallel.
// grid = (T1*4, 32); each block one 64x64 tile (64 b-rows, fixed t).
// ---------------------------------------------------------------------------
__global__ void __launch_bounds__(NT) pre_gemm_kernel(const float* __restrict__ weighted,
                                                      const float* __restrict__ wih,
                                                      const float* __restrict__ bih,
                                                      const float* __restrict__ bhh) {
    __shared__ float sA[16 * 64];
    __shared__ float sB[16 * 64];
    int tstep = blockIdx.x >> 2;
    int b0    = (blockIdx.x & 3) * 64;
    int col0  = blockIdx.y * 64;
    float acc[4][4] = {};
    // A row (b0+m): weighted + (b0+m)*T1*D + tstep*D
    mm_tile(weighted + (size_t)tstep * D, T1 * D, wih, 512, b0, col0, acc, sA, sB);
    int tx = threadIdx.x & 15, ty = threadIdx.x >> 4;
    size_t base = (size_t)tstep * B * G;
#pragma unroll
    for (int i = 0; i < 4; i++)
#pragma unroll
        for (int j = 0; j < 4; j++) {
            int bb = b0 + ty * 4 + i;
            int c  = col0 + tx * 4 + j;
            g_pre0[base + (size_t)bb * G + c] = acc[i][j] + bih[c] + bhh[c];
        }
}

// ---------------------------------------------------------------------------
// Kernel 3: persistent recurrent kernel. 128 blocks, software grid barriers.
// Per step:  phase1: gates[l] = h[l]@W_hh[l]^T (+pre0 / +biases)   [3 tiles/block]
//            ew(l=0) | gates1 += h0@W_ih1^T | ew(1) | gates2 += h1@W_ih2^T | ew(2)
// ---------------------------------------------------------------------------
__global__ void __launch_bounds__(NT, 1) lstm_kernel(const float* __restrict__ wih,
                                                     const float* __restrict__ whh,
                                                     const float* __restrict__ bih,
                                                     const float* __restrict__ bhh,
                                                     float* __restrict__ out) {
    __shared__ float sA[16 * 64];
    __shared__ float sB[16 * 64];

    // zero-init h, c
    for (int idx = blockIdx.x * NT + threadIdx.x; idx < NL * B * H; idx += GRID * NT) {
        ((float*)g_h)[idx] = 0.f;
        ((float*)g_c)[idx] = 0.f;
    }
    grid_barrier();

    const int tile = blockIdx.x;         // 0..127
    const int row0 = (tile >> 5) * 64;   // 4 row tiles over B=256
    const int col0 = (tile & 31) * 64;   // 32 col tiles over G=2048
    const int tx = threadIdx.x & 15, ty = threadIdx.x >> 4;

    for (int t = 0; t < T1; t++) {
        // ---- phase 1: recurrent W_hh GEMMs for all 3 layers ----
        for (int l = 0; l < NL; l++) {
            float acc[4][4] = {};
            mm_tile(g_h[l], H, whh + (size_t)l * G * H, H, row0, col0, acc, sA, sB);
            if (l == 0) {
                size_t pbase = (size_t)t * B * G;
#pragma unroll
                for (int i = 0; i < 4; i++)
#pragma unroll
                    for (int j = 0; j < 4; j++) {
                        int r = row0 + ty * 4 + i, c = col0 + tx * 4 + j;
                        g_gates[0][(size_t)r * G + c] = acc[i][j] + g_pre0[pbase + (size_t)r * G + c];
                    }
            } else {
#pragma unroll
                for (int i = 0; i < 4; i++)
#pragma unroll
                    for (int j = 0; j < 4; j++) {
                        int r = row0 + ty * 4 + i, c = col0 + tx * 4 + j;
                        g_gates[l][(size_t)r * G + c] = acc[i][j] + bih[l * G + c] + bhh[l * G + c];
                    }
            }
        }
        grid_barrier();

        // ---- layer 0 cell update ----
        lstm_ew(0, t, out);
        grid_barrier();

        // ---- gates1 += h0_new @ W_ih[1]^T ----
        {
            float acc[4][4] = {};
            mm_tile(g_h[0], H, wih + (size_t)1 * G * H, H, row0, col0, acc, sA, sB);
#pragma unroll
            for (int i = 0; i < 4; i++)
#pragma unroll
                for (int j = 0; j < 4; j++) {
                    int r = row0 + ty * 4 + i, c = col0 + tx * 4 + j;
                    g_gates[1][(size_t)r * G + c] += acc[i][j];
                }
        }
        grid_barrier();

        // ---- layer 1 cell update ----
        lstm_ew(1, t, out);
        grid_barrier();

        // ---- gates2 += h1_new @ W_ih[2]^T ----
        {
            float acc[4][4] = {};
            mm_tile(g_h[1], H, wih + (size_t)2 * G * H, H, row0, col0, acc, sA, sB);
#pragma unroll
            for (int i = 0; i < 4; i++)
#pragma unroll
                for (int j = 0; j < 4; j++) {
                    int r = row0 + ty * 4 + i, c = col0 + tx * 4 + j;
                    g_gates[2][(size_t)r * G + c] += acc[i][j];
                }
        }
        grid_barrier();

        // ---- layer 2 cell update + write input_encoded ----
        lstm_ew(2, t, out);
        grid_barrier();
    }
}

// ---------------------------------------------------------------------------
extern "C" void kernel_launch(void* const* d_in, const int* in_sizes, int n_in,
                              void* d_out, int out_size) {
    const float* x   = (const float*)d_in[0];  // [B, T1, D]
    const float* wih = (const float*)d_in[1];  // [3, 2048, 512]
    const float* whh = (const float*)d_in[2];  // [3, 2048, 512]
    const float* bih = (const float*)d_in[3];  // [3, 2048]
    const float* bhh = (const float*)d_in[4];  // [3, 2048]
    const float* aw  = (const float*)d_in[5];  // [2H + T1, 1]
    float* out = (float*)d_out;                // [B*T1*D weighted | B*T1*H encoded]

    // 1) attention weights (time-invariant) + input_weighted output
    attn_kernel<<<B, 512>>>(x, aw, out);

    // 2) precompute layer-0 input gates for all timesteps
    dim3 pgrid(T1 * 4, G / 64);
    pre_gemm_kernel<<<pgrid, NT>>>(out, wih, bih, bhh);

    // 3) persistent recurrent kernel
    lstm_kernel<<<GRID, NT>>>(wih, whh, bih, bhh, out);
}